// round 2
// baseline (speedup 1.0000x reference)
#include <cuda_runtime.h>
#include <cstdint>

// Problem constants (Gemma4 attention): B=2, S=2048, D=2048, H=16, KV=4, HD=256
#define Bc 2
#define Sc 2048
#define Dc 2048
#define Hc 16
#define KVc 4
#define HDc 256

// Scratch (no cudaMalloc allowed): ~168 MB of __device__ globals
__device__ float g_q[(size_t)Bc * Sc * Hc * HDc];     // [B,S,H,HD]   67 MB
__device__ float g_k[(size_t)Bc * Sc * KVc * HDc];    // [B,S,KV,HD]  17 MB
__device__ float g_v[(size_t)Bc * Sc * KVc * HDc];    // [B,S,KV,HD]  17 MB
__device__ float g_attn[(size_t)Bc * Sc * Hc * HDc];  // [B,S,H,HD]   67 MB

// ---------------------------------------------------------------------------
// SGEMM: C[M,N] = A[M,K] @ B[K,N], all row-major fp32.
// Block tile 128x64, K-step 16, 256 threads, 8x4 microtile per thread.
// ---------------------------------------------------------------------------
__global__ __launch_bounds__(256) void sgemm128x64(
    const float* __restrict__ A, const float* __restrict__ B,
    float* __restrict__ C, int M, int N, int K)
{
    __shared__ float As[16][132];   // transposed A tile, padded
    __shared__ float Bs[16][64];
    const int tid = threadIdx.x;
    const int tx = tid & 15;        // 0..15 -> N cols (x4)
    const int ty = tid >> 4;        // 0..15 -> M rows (x8)
    const int m0 = blockIdx.y * 128;
    const int n0 = blockIdx.x * 64;

    float acc[8][4];
#pragma unroll
    for (int i = 0; i < 8; i++)
#pragma unroll
        for (int j = 0; j < 4; j++) acc[i][j] = 0.f;

    const float* Ap = A + (size_t)m0 * K;
    const float* Bp = B + n0;

    for (int k0 = 0; k0 < K; k0 += 16) {
        // Load A tile 128x16 (512 float4, 2 per thread), store transposed
#pragma unroll
        for (int li = 0; li < 2; li++) {
            int idx = tid + li * 256;
            int r = idx >> 2;            // 0..127
            int c4 = (idx & 3) << 2;     // 0,4,8,12
            float4 a = *(const float4*)(Ap + (size_t)r * K + k0 + c4);
            As[c4 + 0][r] = a.x;
            As[c4 + 1][r] = a.y;
            As[c4 + 2][r] = a.z;
            As[c4 + 3][r] = a.w;
        }
        // Load B tile 16x64 (256 float4, 1 per thread)
        {
            int r = tid >> 4;            // 0..15
            int c4 = (tid & 15) << 2;    // 0..60
            *(float4*)(&Bs[r][c4]) = *(const float4*)(Bp + (size_t)(k0 + r) * N + c4);
        }
        __syncthreads();
#pragma unroll
        for (int kk = 0; kk < 16; kk++) {
            float4 a1 = *(const float4*)(&As[kk][ty * 8]);
            float4 a2 = *(const float4*)(&As[kk][ty * 8 + 4]);
            float4 b  = *(const float4*)(&Bs[kk][tx * 4]);
            float av[8] = {a1.x, a1.y, a1.z, a1.w, a2.x, a2.y, a2.z, a2.w};
            float bv[4] = {b.x, b.y, b.z, b.w};
#pragma unroll
            for (int i = 0; i < 8; i++)
#pragma unroll
                for (int j = 0; j < 4; j++)
                    acc[i][j] += av[i] * bv[j];
        }
        __syncthreads();
    }
#pragma unroll
    for (int i = 0; i < 8; i++) {
        float4 v = make_float4(acc[i][0], acc[i][1], acc[i][2], acc[i][3]);
        *(float4*)(C + (size_t)(m0 + ty * 8 + i) * N + n0 + tx * 4) = v;
    }
}

// ---------------------------------------------------------------------------
// Fused RMSNorm (eps=1e-6, weight (1+w)) + RoPE (theta=10000), in place.
// buf layout [B,S,nh,HD]; one block (256 threads) per (b,s,head).
// ---------------------------------------------------------------------------
__global__ __launch_bounds__(256) void rmsnorm_rope(
    float* __restrict__ buf, const float* __restrict__ w,
    const int* __restrict__ pos_ids, int nh)
{
    const int blk = blockIdx.x;          // (b*S+s)*nh + head
    const int d = threadIdx.x;           // 0..255
    const int s = (blk / nh) % Sc;
    float* x = buf + (size_t)blk * HDc;
    float v = x[d];

    float sq = v * v;
#pragma unroll
    for (int o = 16; o; o >>= 1) sq += __shfl_xor_sync(0xffffffffu, sq, o);
    __shared__ float red[8];
    __shared__ float ys[256];
    if ((d & 31) == 0) red[d >> 5] = sq;
    __syncthreads();
    float tot = red[0] + red[1] + red[2] + red[3] + red[4] + red[5] + red[6] + red[7];
    float rstd = rsqrtf(tot * (1.0f / 256.0f) + 1e-6f);
    float y = v * rstd * (1.0f + w[d]);
    ys[d] = y;
    __syncthreads();
    float partner = (d < 128) ? -ys[d + 128] : ys[d - 128];

    float p = (float)pos_ids[s];
    float inv_freq = powf(10000.0f, -(float)(d & 127) * (1.0f / 128.0f));
    float ang = p * inv_freq;
    x[d] = y * cosf(ang) + partner * sinf(ang);
}

// ---------------------------------------------------------------------------
// Flash attention, fp32, causal, GQA (kv head = h>>2), scale = 1/16.
// Grid (S/64, H, B); 256 threads = 8 warps; each warp owns 8 q rows,
// lane = key within the current 32-key tile. acc distributed: lane holds
// dims {lane, lane+32, ..., lane+224} -> 8 floats per row per lane.
// Smem rows padded to 260 floats: conflict-free float4 k-loads and
// conflict-free scalar v-loads.
// ---------------------------------------------------------------------------
#define FPAD 260
__global__ __launch_bounds__(256, 1) void flash_attn(
    const float* __restrict__ qb, const float* __restrict__ kb,
    const float* __restrict__ vb, float* __restrict__ ob)
{
    extern __shared__ float sm[];
    float* qs = sm;                  // 64 * FPAD
    float* ks = sm + 64 * FPAD;      // 32 * FPAD
    float* vs = sm + 96 * FPAD;      // 32 * FPAD
    const int q0 = blockIdx.x * 64;
    const int h  = blockIdx.y;
    const int b  = blockIdx.z;
    const int kvh = h >> 2;
    const int tid = threadIdx.x;
    const int w = tid >> 5, lane = tid & 31;

    // Load Q tile (64 rows x 256)
    for (int idx = tid; idx < 64 * 64; idx += 256) {
        int r = idx >> 6;
        int c4 = (idx & 63) << 2;
        float4 v = *(const float4*)(qb + ((size_t)((b * Sc + q0 + r) * Hc + h)) * HDc + c4);
        *(float4*)(qs + r * FPAD + c4) = v;
    }

    float acc[8][8];
#pragma unroll
    for (int r = 0; r < 8; r++)
#pragma unroll
        for (int i = 0; i < 8; i++) acc[r][i] = 0.f;
    float m[8], l[8];
#pragma unroll
    for (int r = 0; r < 8; r++) { m[r] = -3.0e38f; l[r] = 0.f; }

    const int qg_base = q0 + w * 8;
    const int ntiles = (q0 + 64) >> 5;   // causal: keys 0 .. q0+63

    for (int t = 0; t < ntiles; t++) {
        const int j0 = t << 5;
        __syncthreads();
        // Load K/V tiles (32 rows x 256 each)
        for (int idx = tid; idx < 32 * 64; idx += 256) {
            int r = idx >> 6;
            int c4 = (idx & 63) << 2;
            size_t g = ((size_t)((b * Sc + j0 + r) * KVc + kvh)) * HDc + c4;
            *(float4*)(ks + r * FPAD + c4) = *(const float4*)(kb + g);
            *(float4*)(vs + r * FPAD + c4) = *(const float4*)(vb + g);
        }
        __syncthreads();

        // Scores: sc[r] = q[row r] . k[lane]
        float sc[8];
#pragma unroll
        for (int r = 0; r < 8; r++) sc[r] = 0.f;
        for (int d4 = 0; d4 < 256; d4 += 4) {
            float4 k4 = *(const float4*)(ks + lane * FPAD + d4);
#pragma unroll
            for (int r = 0; r < 8; r++) {
                float4 q4 = *(const float4*)(qs + (w * 8 + r) * FPAD + d4);
                sc[r] += q4.x * k4.x + q4.y * k4.y + q4.z * k4.z + q4.w * k4.w;
            }
        }

        // Online softmax update
        const int j = j0 + lane;
        float p[8];
#pragma unroll
        for (int r = 0; r < 8; r++) {
            int qg = qg_base + r;
            float s = (j <= qg) ? sc[r] * 0.0625f : -3.0e38f;
            float mx = s;
#pragma unroll
            for (int o = 16; o; o >>= 1)
                mx = fmaxf(mx, __shfl_xor_sync(0xffffffffu, mx, o));
            float mnew = fmaxf(m[r], mx);
            float pv = __expf(s - mnew);
            float alpha = __expf(m[r] - mnew);
            m[r] = mnew;
            float ps = pv;
#pragma unroll
            for (int o = 16; o; o >>= 1)
                ps += __shfl_xor_sync(0xffffffffu, ps, o);
            l[r] = l[r] * alpha + ps;
#pragma unroll
            for (int i = 0; i < 8; i++) acc[r][i] *= alpha;
            p[r] = pv;
        }

        // acc += P @ V
#pragma unroll 4
        for (int key = 0; key < 32; key++) {
            float vv[8];
#pragma unroll
            for (int i = 0; i < 8; i++) vv[i] = vs[key * FPAD + lane + 32 * i];
#pragma unroll
            for (int r = 0; r < 8; r++) {
                float pk = __shfl_sync(0xffffffffu, p[r], key);
#pragma unroll
                for (int i = 0; i < 8; i++) acc[r][i] += pk * vv[i];
            }
        }
    }

    // Epilogue: out = acc / l, layout [B,S,H,HD]
#pragma unroll
    for (int r = 0; r < 8; r++) {
        int qg = qg_base + r;
        float inv = 1.0f / l[r];
        float* op = ob + ((size_t)((b * Sc + qg) * Hc + h)) * HDc;
#pragma unroll
        for (int i = 0; i < 8; i++) op[lane + 32 * i] = acc[r][i] * inv;
    }
}

// ---------------------------------------------------------------------------
extern "C" void kernel_launch(void* const* d_in, const int* in_sizes, int n_in,
                              void* d_out, int out_size)
{
    const float* hidden = (const float*)d_in[0];   // [B,S,D]
    const float* Wq = (const float*)d_in[1];       // [D, H*HD]
    const float* Wk = (const float*)d_in[2];       // [D, KV*HD]
    const float* Wv = (const float*)d_in[3];       // [D, KV*HD]
    const float* Wo = (const float*)d_in[4];       // [H*HD, D]
    const float* qw = (const float*)d_in[5];       // [HD]
    const float* kw = (const float*)d_in[6];       // [HD]
    const int*  pos = (const int*)d_in[7];         // [S]
    float* out = (float*)d_out;                    // [B,S,D]

    float *qb, *kb, *vb, *ab;
    cudaGetSymbolAddress((void**)&qb, g_q);
    cudaGetSymbolAddress((void**)&kb, g_k);
    cudaGetSymbolAddress((void**)&vb, g_v);
    cudaGetSymbolAddress((void**)&ab, g_attn);

    const int M = Bc * Sc;  // 4096

    // QKV projections
    sgemm128x64<<<dim3((Hc * HDc) / 64, M / 128), 256>>>(hidden, Wq, qb, M, Hc * HDc, Dc);
    sgemm128x64<<<dim3((KVc * HDc) / 64, M / 128), 256>>>(hidden, Wk, kb, M, KVc * HDc, Dc);
    sgemm128x64<<<dim3((KVc * HDc) / 64, M / 128), 256>>>(hidden, Wv, vb, M, KVc * HDc, Dc);

    // RMSNorm + RoPE (in place) on Q and K
    rmsnorm_rope<<<M * Hc, 256>>>(qb, qw, pos, Hc);
    rmsnorm_rope<<<M * KVc, 256>>>(kb, kw, pos, KVc);

    // Flash attention
    size_t shmem = (size_t)128 * FPAD * sizeof(float);  // 133120 B
    cudaFuncSetAttribute(flash_attn, cudaFuncAttributeMaxDynamicSharedMemorySize, (int)shmem);
    flash_attn<<<dim3(Sc / 64, Hc, Bc), 256, shmem>>>(qb, kb, vb, ab);

    // Output projection
    sgemm128x64<<<dim3(Dc / 64, M / 128), 256>>>(ab, Wo, out, M, Dc, Hc * HDc);
}